// round 2
// baseline (speedup 1.0000x reference)
#include <cuda_runtime.h>
#include <cstdint>

#define BATCH 256
#define L 4096
#define H 128
#define NT 512

// ---------- packed f32x2 helpers (Blackwell sm_103a) ----------
__device__ __forceinline__ uint64_t pack2f(float a, float b) {
    uint64_t r; asm("mov.b64 %0, {%1, %2};" : "=l"(r) : "f"(a), "f"(b)); return r;
}
__device__ __forceinline__ float hsum2(uint64_t v) {
    float a, b; asm("mov.b64 {%0, %1}, %2;" : "=f"(a), "=f"(b) : "l"(v)); return a + b;
}
__device__ __forceinline__ uint64_t ffma2(uint64_t a, uint64_t b, uint64_t c) {
    uint64_t d; asm("fma.rn.f32x2 %0, %1, %2, %3;" : "=l"(d) : "l"(a), "l"(b), "l"(c)); return d;
}
__device__ __forceinline__ uint64_t fadd2(uint64_t a, uint64_t b) {
    uint64_t d; asm("add.rn.f32x2 %0, %1, %2;" : "=l"(d) : "l"(a), "l"(b)); return d;
}
__device__ __forceinline__ float elu1(float x) {
    return x > 0.f ? x : (__expf(x) - 1.f);
}

// One CTA = 2 batch elements, 512 threads = (i, s):
//   i = tid>>2 in [0,128): output hidden unit
//   s = tid&3:  k-quarter owner (k = 16j + 4s + m, j=0..7, m=0..3)
// Thread (i,s) holds W_c[l][k][i] for its k-quarter in registers (packed f32x2)
// and computes quarter-dots for BOTH batches. Quarter partials meet via
// shfl_xor(1) + shfl_xor(2). h vectors ping-pong in SMEM (1 barrier/step).
// The output head (logit/log-softmax) is DEFERRED one step and computed by
// warps 14/15 from the same parity buffer layer-2 reads — off the critical path.
__global__ void __launch_bounds__(NT, 1)
rnn_scan_kernel(const int* __restrict__ x,
                const float* __restrict__ W_in,
                const float* __restrict__ W_c,
                const float* __restrict__ W_out,
                const float* __restrict__ b_out,
                float* __restrict__ out)
{
    __shared__ __align__(16) float sh_h1[2][2 * H];   // [parity][batch*H]
    __shared__ __align__(16) float sh_h2[2][2 * H];
    __shared__ float sh_r[3 * H];                     // r for spin0, spin1, zero-prev
    __shared__ int   sh_x[2 * L];                     // both batch rows of x (32 KB)

    const int tid  = threadIdx.x;
    const int warp = tid >> 5;
    const int lane = tid & 31;
    const int i    = tid >> 2;     // output unit
    const int s    = tid & 3;      // k-quarter
    const int b0   = blockIdx.x * 2;

    // ---- stage x (coalesced) ----
    const int* xg = x + (size_t)b0 * L;
    #pragma unroll 4
    for (int idx = tid; idx < 2 * L; idx += NT) sh_x[idx] = xg[idx];

    // ---- precompute the 3 possible r vectors; zero parity-0 h ----
    if (tid < 2 * H) sh_r[tid] = elu1(W_in[tid]);
    if (tid < H)     sh_r[2 * H + tid] = 0.f;
    if (tid < 2 * H) { sh_h1[0][tid] = 0.f; sh_h2[0][tid] = 0.f; }

    // ---- load W_c quarter-columns into registers (packed pairs) ----
    uint64_t w1p[16], w2p[16];
    {
        const float* Wc0 = W_c;
        const float* Wc1 = W_c + H * H;
        #pragma unroll
        for (int j = 0; j < 8; ++j) {
            const int k0 = 16 * j + 4 * s;
            w1p[2*j]   = pack2f(Wc0[(k0+0)*H + i], Wc0[(k0+1)*H + i]);
            w1p[2*j+1] = pack2f(Wc0[(k0+2)*H + i], Wc0[(k0+3)*H + i]);
            w2p[2*j]   = pack2f(Wc1[(k0+0)*H + i], Wc1[(k0+1)*H + i]);
            w2p[2*j+1] = pack2f(Wc1[(k0+2)*H + i], Wc1[(k0+3)*H + i]);
        }
    }

    // ---- deferred output-head state (warps 14,15 only) ----
    uint64_t woutp0 = 0, woutp1 = 0;
    float bout = 0.f, acc = 0.f;
    if (warp >= 14) {
        const float4 w4 = *(const float4*)(W_out + 4 * lane);
        woutp0 = pack2f(w4.x, w4.y);
        woutp1 = pack2f(w4.z, w4.w);
        bout = b_out[0];
    }
    __syncthreads();

    for (int t = 0; t < L; ++t) {
        const int p = t & 1;
        const float* h1r = &sh_h1[p][0];
        float*       h1w = &sh_h1[p ^ 1][0];
        const float* h2r = &sh_h2[p][0];
        float*       h2w = &sh_h2[p ^ 1][0];

        // ================= layer 1 quarter-matvec (both batches) =================
        uint64_t a00 = 0, a01 = 0, a10 = 0, a11 = 0;
        #pragma unroll
        for (int j = 0; j < 8; ++j) {
            const int o = 16 * j + 4 * s;
            const ulonglong2 hv0 = *(const ulonglong2*)(h1r + o);
            const ulonglong2 hv1 = *(const ulonglong2*)(h1r + H + o);
            a00 = ffma2(w1p[2*j],   hv0.x, a00);
            a01 = ffma2(w1p[2*j+1], hv0.y, a01);
            a10 = ffma2(w1p[2*j],   hv1.x, a10);
            a11 = ffma2(w1p[2*j+1], hv1.y, a11);
        }
        float p0 = hsum2(fadd2(a00, a01));
        float p1 = hsum2(fadd2(a10, a11));
        p0 += __shfl_xor_sync(0xffffffffu, p0, 1);
        p0 += __shfl_xor_sync(0xffffffffu, p0, 2);
        p1 += __shfl_xor_sync(0xffffffffu, p1, 1);
        p1 += __shfl_xor_sync(0xffffffffu, p1, 2);

        // finalize (writer lanes: s==0 -> batch0, s==1 -> batch1)
        float hn = 0.f;
        if (s < 2) {
            const int prev = (t == 0) ? 2 : sh_x[s * L + t - 1];
            hn = elu1(s ? p1 : p0) + sh_r[prev * H + i];
            h1w[s * H + i] = hn;
        }

        // ================= layer 2 quarter-matvec =================
        uint64_t c00 = 0, c01 = 0, c10 = 0, c11 = 0;
        #pragma unroll
        for (int j = 0; j < 8; ++j) {
            const int o = 16 * j + 4 * s;
            const ulonglong2 hv0 = *(const ulonglong2*)(h2r + o);
            const ulonglong2 hv1 = *(const ulonglong2*)(h2r + H + o);
            c00 = ffma2(w2p[2*j],   hv0.x, c00);
            c01 = ffma2(w2p[2*j+1], hv0.y, c01);
            c10 = ffma2(w2p[2*j],   hv1.x, c10);
            c11 = ffma2(w2p[2*j+1], hv1.y, c11);
        }
        float q0 = hsum2(fadd2(c00, c01));
        float q1 = hsum2(fadd2(c10, c11));
        q0 += __shfl_xor_sync(0xffffffffu, q0, 1);
        q0 += __shfl_xor_sync(0xffffffffu, q0, 2);
        q1 += __shfl_xor_sync(0xffffffffu, q1, 1);
        q1 += __shfl_xor_sync(0xffffffffu, q1, 2);

        if (s < 2) {
            const float h2n = elu1(s ? q1 : q0) + hn;
            h2w[s * H + i] = h2n;
        }

        // ===== deferred output head: logit(t-1) from sh_h2[p] (warps 14,15) =====
        if (warp >= 14 && t > 0) {
            const int b = warp - 14;
            const ulonglong2 hv = *(const ulonglong2*)(h2r + b * H + 4 * lane);
            uint64_t d = ffma2(woutp0, hv.x, (uint64_t)0);
            d = ffma2(woutp1, hv.y, d);
            float term = hsum2(d);
            #pragma unroll
            for (int off = 16; off; off >>= 1)
                term += __shfl_xor_sync(0xffffffffu, term, off);
            const float logit = term + bout;
            const int   xt  = sh_x[b * L + t - 1];
            const float m   = fmaxf(logit, 0.f);
            const float lse = m + __logf(__expf(-m) + __expf(logit - m));
            acc += 0.5f * ((xt ? logit : 0.f) - lse);
        }

        __syncthreads();   // single barrier per step
    }

    // ---- final step's logit: h2(L-1) is in sh_h2[0] (L even) ----
    if (warp >= 14) {
        const int b = warp - 14;
        const float* h2f = &sh_h2[0][0];
        const ulonglong2 hv = *(const ulonglong2*)(h2f + b * H + 4 * lane);
        uint64_t d = ffma2(woutp0, hv.x, (uint64_t)0);
        d = ffma2(woutp1, hv.y, d);
        float term = hsum2(d);
        #pragma unroll
        for (int off = 16; off; off >>= 1)
            term += __shfl_xor_sync(0xffffffffu, term, off);
        const float logit = term + bout;
        const int   xt  = sh_x[b * L + L - 1];
        const float m   = fmaxf(logit, 0.f);
        const float lse = m + __logf(__expf(-m) + __expf(logit - m));
        acc += 0.5f * ((xt ? logit : 0.f) - lse);
        if (lane == 0) out[b0 + b] = acc;
    }
}

extern "C" void kernel_launch(void* const* d_in, const int* in_sizes, int n_in,
                              void* d_out, int out_size)
{
    const int*   x     = (const int*)  d_in[0];
    const float* W_in  = (const float*)d_in[1];
    const float* W_c   = (const float*)d_in[2];
    const float* W_out = (const float*)d_in[3];
    const float* b_out = (const float*)d_in[4];

    rnn_scan_kernel<<<BATCH / 2, NT>>>(x, W_in, W_c, W_out, b_out, (float*)d_out);
}

// round 3
// speedup vs baseline: 1.6913x; 1.6913x over previous
#include <cuda_runtime.h>
#include <cstdint>

#define BATCH 256
#define L 4096
#define H 128

// ---------- packed f32x2 helpers (Blackwell sm_103a) ----------
__device__ __forceinline__ uint64_t pack2f(float a, float b) {
    uint64_t r; asm("mov.b64 %0, {%1, %2};" : "=l"(r) : "f"(a), "f"(b)); return r;
}
__device__ __forceinline__ float hsum2(uint64_t v) {
    float a, b; asm("mov.b64 {%0, %1}, %2;" : "=f"(a), "=f"(b) : "l"(v)); return a + b;
}
__device__ __forceinline__ uint64_t ffma2(uint64_t a, uint64_t b, uint64_t c) {
    uint64_t d; asm("fma.rn.f32x2 %0, %1, %2, %3;" : "=l"(d) : "l"(a), "l"(b), "l"(c)); return d;
}
__device__ __forceinline__ uint64_t fadd2(uint64_t a, uint64_t b) {
    uint64_t d; asm("add.rn.f32x2 %0, %1, %2;" : "=l"(d) : "l"(a), "l"(b)); return d;
}
__device__ __forceinline__ float elu1(float x) {
    return x > 0.f ? x : (__expf(x) - 1.f);
}

// One CTA = 2 batch elements, 256 threads = (i, s):
//   i = tid>>1 in [0,128): output hidden unit;  s = tid&1: k-half owner.
// Thread (i,s) holds its k-half of W_c columns for both layers in registers
// (128 f32 = 64 packed regs). h ping-pongs in SMEM; the two k-half partials
// meet via one shfl_xor(1). One __syncthreads per step.
// The output head (logit -> log-softmax) is DEFERRED one step: warps 6 & 7
// compute logit(t-1) for batch 0/1 from the parity buffer layer-2 already
// reads — entirely off the h-recurrence critical path.
__global__ void __launch_bounds__(256, 1)
rnn_scan_kernel(const int* __restrict__ x,
                const float* __restrict__ W_in,
                const float* __restrict__ W_c,
                const float* __restrict__ W_out,
                const float* __restrict__ b_out,
                float* __restrict__ out)
{
    __shared__ __align__(16) float sh_h1[2][2 * H];   // [parity][batch*H]
    __shared__ __align__(16) float sh_h2[2][2 * H];
    __shared__ float sh_r[3 * H];                     // r for spin0, spin1, zero-prev
    __shared__ int   sh_x[2 * L];                     // both batch rows of x (32 KB)

    const int tid  = threadIdx.x;
    const int warp = tid >> 5;
    const int lane = tid & 31;
    const int i    = tid >> 1;     // output unit
    const int s    = tid & 1;      // k-half (also: which batch this thread writes)
    const int b0   = blockIdx.x * 2;

    // ---- stage x (coalesced) ----
    const int* xg = x + (size_t)b0 * L;
    #pragma unroll 4
    for (int idx = tid; idx < 2 * L; idx += 256) sh_x[idx] = xg[idx];

    // ---- precompute the 3 possible r vectors; zero parity-0 h ----
    if (tid < 2 * H) sh_r[tid] = elu1(W_in[tid]);
    if (tid < H)     sh_r[2 * H + tid] = 0.f;
    if (tid < 2 * H) { sh_h1[0][tid] = 0.f; sh_h2[0][tid] = 0.f; }

    // ---- load W_c half-columns into registers (packed pairs) ----
    uint64_t w1p[32], w2p[32];
    {
        const float* Wc0 = W_c;
        const float* Wc1 = W_c + H * H;
        #pragma unroll
        for (int j = 0; j < 16; ++j) {
            const int k0 = 8 * j + 4 * s;
            w1p[2*j]   = pack2f(Wc0[(k0+0)*H + i], Wc0[(k0+1)*H + i]);
            w1p[2*j+1] = pack2f(Wc0[(k0+2)*H + i], Wc0[(k0+3)*H + i]);
            w2p[2*j]   = pack2f(Wc1[(k0+0)*H + i], Wc1[(k0+1)*H + i]);
            w2p[2*j+1] = pack2f(Wc1[(k0+2)*H + i], Wc1[(k0+3)*H + i]);
        }
    }

    // ---- deferred output-head state (warps 6,7 only) ----
    uint64_t woutp0 = 0, woutp1 = 0;
    float bout = 0.f, acc = 0.f;
    if (warp >= 6) {
        const float4 w4 = *(const float4*)(W_out + 4 * lane);
        woutp0 = pack2f(w4.x, w4.y);
        woutp1 = pack2f(w4.z, w4.w);
        bout = b_out[0];
    }
    __syncthreads();

    for (int t = 0; t < L; ++t) {
        const int p = t & 1;
        const float* h1r = &sh_h1[p][0];
        float*       h1w = &sh_h1[p ^ 1][0];
        const float* h2r = &sh_h2[p][0];
        float*       h2w = &sh_h2[p ^ 1][0];

        // hoist the spin / r lookups so their LDS latency hides under the FMAs
        const int   prev = (t == 0) ? 2 : sh_x[s * L + t - 1];
        const float rv   = sh_r[prev * H + i];

        // ================= layer 1 half-matvec (both batches) =================
        uint64_t a00 = 0, a01 = 0, a10 = 0, a11 = 0;
        #pragma unroll
        for (int j = 0; j < 16; ++j) {
            const int o = 8 * j + 4 * s;
            const ulonglong2 hv0 = *(const ulonglong2*)(h1r + o);
            const ulonglong2 hv1 = *(const ulonglong2*)(h1r + H + o);
            a00 = ffma2(w1p[2*j],   hv0.x, a00);
            a01 = ffma2(w1p[2*j+1], hv0.y, a01);
            a10 = ffma2(w1p[2*j],   hv1.x, a10);
            a11 = ffma2(w1p[2*j+1], hv1.y, a11);
        }
        float p0 = hsum2(fadd2(a00, a01));
        float p1 = hsum2(fadd2(a10, a11));
        p0 += __shfl_xor_sync(0xffffffffu, p0, 1);
        p1 += __shfl_xor_sync(0xffffffffu, p1, 1);

        // finalize batch 's': h1_new = elu(h1 @ Wc0) + r
        const float h1n = elu1(s ? p1 : p0) + rv;
        h1w[s * H + i] = h1n;

        // ================= layer 2 half-matvec =================
        uint64_t c00 = 0, c01 = 0, c10 = 0, c11 = 0;
        #pragma unroll
        for (int j = 0; j < 16; ++j) {
            const int o = 8 * j + 4 * s;
            const ulonglong2 hv0 = *(const ulonglong2*)(h2r + o);
            const ulonglong2 hv1 = *(const ulonglong2*)(h2r + H + o);
            c00 = ffma2(w2p[2*j],   hv0.x, c00);
            c01 = ffma2(w2p[2*j+1], hv0.y, c01);
            c10 = ffma2(w2p[2*j],   hv1.x, c10);
            c11 = ffma2(w2p[2*j+1], hv1.y, c11);
        }
        float q0 = hsum2(fadd2(c00, c01));
        float q1 = hsum2(fadd2(c10, c11));
        q0 += __shfl_xor_sync(0xffffffffu, q0, 1);
        q1 += __shfl_xor_sync(0xffffffffu, q1, 1);

        const float h2n = elu1(s ? q1 : q0) + h1n;
        h2w[s * H + i] = h2n;

        // ===== deferred output head: logit(t-1) from sh_h2[p] (warps 6,7) =====
        if (warp >= 6 && t > 0) {
            const int b = warp - 6;
            const ulonglong2 hv = *(const ulonglong2*)(h2r + b * H + 4 * lane);
            uint64_t d = ffma2(woutp0, hv.x, (uint64_t)0);
            d = ffma2(woutp1, hv.y, d);
            float term = hsum2(d);
            #pragma unroll
            for (int off = 16; off; off >>= 1)
                term += __shfl_xor_sync(0xffffffffu, term, off);
            const float logit = term + bout;
            const int   xt  = sh_x[b * L + t - 1];
            const float m   = fmaxf(logit, 0.f);
            const float lse = m + __logf(__expf(-m) + __expf(logit - m));
            acc += 0.5f * ((xt ? logit : 0.f) - lse);
        }

        __syncthreads();   // single barrier per step
    }

    // ---- final step's logit: h2(L-1) lives in sh_h2[0] (L even) ----
    if (warp >= 6) {
        const int b = warp - 6;
        const float* h2f = &sh_h2[0][0];
        const ulonglong2 hv = *(const ulonglong2*)(h2f + b * H + 4 * lane);
        uint64_t d = ffma2(woutp0, hv.x, (uint64_t)0);
        d = ffma2(woutp1, hv.y, d);
        float term = hsum2(d);
        #pragma unroll
        for (int off = 16; off; off >>= 1)
            term += __shfl_xor_sync(0xffffffffu, term, off);
        const float logit = term + bout;
        const int   xt  = sh_x[b * L + L - 1];
        const float m   = fmaxf(logit, 0.f);
        const float lse = m + __logf(__expf(-m) + __expf(logit - m));
        acc += 0.5f * ((xt ? logit : 0.f) - lse);
        if (lane == 0) out[b0 + b] = acc;
    }
}

extern "C" void kernel_launch(void* const* d_in, const int* in_sizes, int n_in,
                              void* d_out, int out_size)
{
    const int*   x     = (const int*)  d_in[0];
    const float* W_in  = (const float*)d_in[1];
    const float* W_c   = (const float*)d_in[2];
    const float* W_out = (const float*)d_in[3];
    const float* b_out = (const float*)d_in[4];

    rnn_scan_kernel<<<BATCH / 2, 256>>>(x, W_in, W_c, W_out, b_out, (float*)d_out);
}

// round 4
// speedup vs baseline: 2.1925x; 1.2964x over previous
#include <cuda_runtime.h>
#include <cstdint>

#define BATCH 256
#define L 4096
#define H 128

// ---------- packed f32x2 helpers (Blackwell sm_103a) ----------
__device__ __forceinline__ uint64_t pack2f(float a, float b) {
    uint64_t r; asm("mov.b64 %0, {%1, %2};" : "=l"(r) : "f"(a), "f"(b)); return r;
}
__device__ __forceinline__ float hsum2(uint64_t v) {
    float a, b; asm("mov.b64 {%0, %1}, %2;" : "=f"(a), "=f"(b) : "l"(v)); return a + b;
}
__device__ __forceinline__ uint64_t ffma2(uint64_t a, uint64_t b, uint64_t c) {
    uint64_t d; asm("fma.rn.f32x2 %0, %1, %2, %3;" : "=l"(d) : "l"(a), "l"(b), "l"(c)); return d;
}
__device__ __forceinline__ uint64_t fadd2(uint64_t a, uint64_t b) {
    uint64_t d; asm("add.rn.f32x2 %0, %1, %2;" : "=l"(d) : "l"(a), "l"(b)); return d;
}
// branchless elu: no BSSY/BSYNC on the critical path
__device__ __forceinline__ float elu1(float x) {
    return fmaxf(x, 0.f) + (__expf(fminf(x, 0.f)) - 1.f);
}

// One CTA = 2 batch elements, 256 threads = (i, s):
//   i = tid>>1 in [0,128): output hidden unit;  s = tid&1: k-half owner (== batch written).
// Thread (i,s) holds its k-half of BOTH layers' W_c columns in registers.
// Per step: ONE fused loop accumulates layer-1 AND layer-2 partials (both read
// the parity-p h buffers; independent until finalize) -> 8 parallel FMA chains.
// Output head: per step only  sh_prod[t&31][tid] = h2n * W_out[i]  (1 STS).
// Every 16 steps each warp bulk-reduces 2 buffered steps (32-slot ring, no race)
// and accumulates log-softmax terms — head cost ~20 cyc/step, no slow warp.
__global__ void __launch_bounds__(256, 1)
rnn_scan_kernel(const int* __restrict__ x,
                const float* __restrict__ W_in,
                const float* __restrict__ W_c,
                const float* __restrict__ W_out,
                const float* __restrict__ b_out,
                float* __restrict__ out)
{
    __shared__ __align__(16) float sh_h1[2][2 * H];     // [parity][batch*H]
    __shared__ __align__(16) float sh_h2[2][2 * H];
    __shared__ float sh_r[3 * H];                       // r for spin0, spin1, zero-prev
    __shared__ __align__(16) float sh_prod[32][256];    // 32 KB ring of h2*wout products
    __shared__ uint8_t sh_x[2 * L];                     // x as bytes (8 KB)
    __shared__ float sh_final[8][2];                    // per-warp acc partials

    const int tid  = threadIdx.x;
    const int warp = tid >> 5;
    const int lane = tid & 31;
    const int i    = tid >> 1;     // output unit
    const int s    = tid & 1;      // k-half / batch written
    const int b0   = blockIdx.x * 2;

    // ---- stage x (coalesced reads, byte writes) ----
    const int* xg = x + (size_t)b0 * L;
    #pragma unroll 4
    for (int idx = tid; idx < 2 * L; idx += 256) sh_x[idx] = (uint8_t)xg[idx];

    // ---- precompute the 3 possible r vectors; zero parity-0 h ----
    if (tid < 2 * H) sh_r[tid] = elu1(W_in[tid]);
    if (tid < H)     sh_r[2 * H + tid] = 0.f;
    if (tid < 2 * H) { sh_h1[0][tid] = 0.f; sh_h2[0][tid] = 0.f; }

    // ---- load W_c half-columns into registers (packed pairs) ----
    uint64_t w1p[32], w2p[32];
    {
        const float* Wc0 = W_c;
        const float* Wc1 = W_c + H * H;
        #pragma unroll
        for (int j = 0; j < 16; ++j) {
            const int k0 = 8 * j + 4 * s;
            w1p[2*j]   = pack2f(Wc0[(k0+0)*H + i], Wc0[(k0+1)*H + i]);
            w1p[2*j+1] = pack2f(Wc0[(k0+2)*H + i], Wc0[(k0+3)*H + i]);
            w2p[2*j]   = pack2f(Wc1[(k0+0)*H + i], Wc1[(k0+1)*H + i]);
            w2p[2*j+1] = pack2f(Wc1[(k0+2)*H + i], Wc1[(k0+3)*H + i]);
        }
    }
    const float wout_i = W_out[i];
    const float bout   = b_out[0];
    float acc0 = 0.f, acc1 = 0.f;     // lane0 keeps batch-0 sum, lane1 batch-1 (per warp)

    __syncthreads();

    for (int t = 0; t < L; ++t) {
        // ===== bulk output head: every 16 steps, warp w reduces steps
        //       u = t-16+2w, t-16+2w+1 from the prod ring (written >=1 barrier ago)
        if ((t & 15) == 0 && t > 0) {
            #pragma unroll
            for (int e = 0; e < 2; ++e) {
                const int u    = t - 16 + 2 * warp + e;
                const int slot = u & 31;
                const float4 v0 = *(const float4*)&sh_prod[slot][lane * 8];
                const float4 v1 = *(const float4*)&sh_prod[slot][lane * 8 + 4];
                float t0 = (v0.x + v0.z) + (v1.x + v1.z);   // batch 0 (even tids)
                float t1 = (v0.y + v0.w) + (v1.y + v1.w);   // batch 1 (odd tids)
                #pragma unroll
                for (int off = 16; off; off >>= 1) {
                    t0 += __shfl_xor_sync(0xffffffffu, t0, off);
                    t1 += __shfl_xor_sync(0xffffffffu, t1, off);
                }
                if (lane < 2) {
                    const float logit = (lane ? t1 : t0) + bout;
                    const int   xt    = sh_x[lane * L + u];
                    const float m     = fmaxf(logit, 0.f);
                    const float lse   = m + __logf(__expf(-m) + __expf(logit - m));
                    const float g     = 0.5f * ((xt ? logit : 0.f) - lse);
                    if (lane == 0) acc0 += g; else acc1 += g;
                }
            }
        }

        const int p = t & 1;
        const float* h1r = &sh_h1[p][0];
        float*       h1w = &sh_h1[p ^ 1][0];
        const float* h2r = &sh_h2[p][0];
        float*       h2w = &sh_h2[p ^ 1][0];

        // hoisted spin / r lookup (hides under the fused FMA stream)
        const int   prev = (t == 0) ? 2 : (int)sh_x[s * L + t - 1];
        const float rv   = sh_r[prev * H + i];

        // ===== fused layer-1 + layer-2 half-matvec (both batches each) =====
        uint64_t a00 = 0, a01 = 0, a10 = 0, a11 = 0;
        uint64_t c00 = 0, c01 = 0, c10 = 0, c11 = 0;
        #pragma unroll
        for (int j = 0; j < 16; ++j) {
            const int o = 8 * j + 4 * s;
            const ulonglong2 g0 = *(const ulonglong2*)(h1r + o);
            const ulonglong2 g1 = *(const ulonglong2*)(h1r + H + o);
            const ulonglong2 e0 = *(const ulonglong2*)(h2r + o);
            const ulonglong2 e1 = *(const ulonglong2*)(h2r + H + o);
            a00 = ffma2(w1p[2*j],   g0.x, a00);
            a01 = ffma2(w1p[2*j+1], g0.y, a01);
            a10 = ffma2(w1p[2*j],   g1.x, a10);
            a11 = ffma2(w1p[2*j+1], g1.y, a11);
            c00 = ffma2(w2p[2*j],   e0.x, c00);
            c01 = ffma2(w2p[2*j+1], e0.y, c01);
            c10 = ffma2(w2p[2*j],   e1.x, c10);
            c11 = ffma2(w2p[2*j+1], e1.y, c11);
        }

        float p0 = hsum2(fadd2(a00, a01));
        float p1 = hsum2(fadd2(a10, a11));
        float q0 = hsum2(fadd2(c00, c01));
        float q1 = hsum2(fadd2(c10, c11));
        p0 += __shfl_xor_sync(0xffffffffu, p0, 1);
        p1 += __shfl_xor_sync(0xffffffffu, p1, 1);
        q0 += __shfl_xor_sync(0xffffffffu, q0, 1);
        q1 += __shfl_xor_sync(0xffffffffu, q1, 1);

        const float h1n = elu1(s ? p1 : p0) + rv;
        h1w[s * H + i] = h1n;
        const float h2n = elu1(s ? q1 : q0) + h1n;
        h2w[s * H + i] = h2n;
        sh_prod[t & 31][tid] = h2n * wout_i;

        __syncthreads();   // single barrier per step
    }

    // ===== epilogue: reduce the last 16 steps =====
    {
        #pragma unroll
        for (int e = 0; e < 2; ++e) {
            const int u    = L - 16 + 2 * warp + e;
            const int slot = u & 31;
            const float4 v0 = *(const float4*)&sh_prod[slot][lane * 8];
            const float4 v1 = *(const float4*)&sh_prod[slot][lane * 8 + 4];
            float t0 = (v0.x + v0.z) + (v1.x + v1.z);
            float t1 = (v0.y + v0.w) + (v1.y + v1.w);
            #pragma unroll
            for (int off = 16; off; off >>= 1) {
                t0 += __shfl_xor_sync(0xffffffffu, t0, off);
                t1 += __shfl_xor_sync(0xffffffffu, t1, off);
            }
            if (lane < 2) {
                const float logit = (lane ? t1 : t0) + bout;
                const int   xt    = sh_x[lane * L + u];
                const float m     = fmaxf(logit, 0.f);
                const float lse   = m + __logf(__expf(-m) + __expf(logit - m));
                const float g     = 0.5f * ((xt ? logit : 0.f) - lse);
                if (lane == 0) acc0 += g; else acc1 += g;
            }
        }
    }

    if (lane == 0) sh_final[warp][0] = acc0;
    if (lane == 1) sh_final[warp][1] = acc1;
    __syncthreads();
    if (tid < 2) {
        float a = 0.f;
        #pragma unroll
        for (int w = 0; w < 8; ++w) a += sh_final[w][tid];
        out[b0 + tid] = a;
    }
}

extern "C" void kernel_launch(void* const* d_in, const int* in_sizes, int n_in,
                              void* d_out, int out_size)
{
    const int*   x     = (const int*)  d_in[0];
    const float* W_in  = (const float*)d_in[1];
    const float* W_c   = (const float*)d_in[2];
    const float* W_out = (const float*)d_in[3];
    const float* b_out = (const float*)d_in[4];

    rnn_scan_kernel<<<BATCH / 2, 256>>>(x, W_in, W_c, W_out, b_out, (float*)d_out);
}